// round 4
// baseline (speedup 1.0000x reference)
#include <cuda_runtime.h>
#include <cuda_bf16.h>
#include <cstdint>

// ---------------- problem constants ----------------
#define KSNAP 8
#define NNODE 10000
#define NEDGE 160000
#define EPTOT (NEDGE + NNODE)   // edges + self loops = 170000
#define HEADS 8
#define D2 256
#define LH 256
#define NEG 0.2f
#define NTOT (KSNAP * NNODE)    // 80000

// ---------------- static scratch ----------------
static __device__ unsigned int g_Ahi [NTOT * 128];     // h1 bf16x2 packed [node][128 words]
static __device__ unsigned int g_Bhi [256 * 128];      // W2 bf16x2 hi [k][128 words]
static __device__ unsigned int g_Blo [256 * 128];      // W2 bf16x2 lo
static __device__ unsigned int g_featb[NTOT * 128];    // h_lin bf16x2 packed
static __device__ float g_ssrc[NTOT * HEADS];
static __device__ float g_sdst[NTOT * HEADS];
static __device__ float g_q   [2 * HEADS];
static __device__ int   g_deg [KSNAP * NNODE];
static __device__ int   g_off [KSNAP * (NNODE + 1)];
static __device__ int   g_pos [KSNAP * NNODE];
static __device__ int   g_adj [KSNAP * EPTOT];
static __device__ float g_emb [KSNAP * D2];
static __device__ float g_xw  [2 * KSNAP * 4 * LH];
static __device__ float2 g_whhT2[2 * 128 * 1024];

// ---------------- generic helpers ----------------
__device__ __forceinline__ float warp_sum(float v) {
#pragma unroll
    for (int o = 16; o; o >>= 1) v += __shfl_xor_sync(0xffffffffu, v, o);
    return v;
}
__device__ __forceinline__ float warp_max(float v) {
#pragma unroll
    for (int o = 16; o; o >>= 1) v = fmaxf(v, __shfl_xor_sync(0xffffffffu, v, o));
    return v;
}
__device__ __forceinline__ float warp_min(float v) {
#pragma unroll
    for (int o = 16; o; o >>= 1) v = fminf(v, __shfl_xor_sync(0xffffffffu, v, o));
    return v;
}
#define FMA2(d, a, b) asm("fma.rn.f32x2 %0, %1, %2, %0;" : "+l"(d) : "l"(a), "l"(b))
__device__ __forceinline__ void unpack2(unsigned long long v, float& lo, float& hi) {
    lo = __uint_as_float((unsigned int)(v & 0xffffffffull));
    hi = __uint_as_float((unsigned int)(v >> 32));
}
__device__ __forceinline__ float lky(float e) { return (e >= 0.f) ? e : NEG * e; }
__device__ __forceinline__ uint32_t pack_bf16x2(float a, float b) {
    __nv_bfloat162 p = __float22bfloat162_rn(make_float2(a, b));
    return *(uint32_t*)&p;
}
__device__ __forceinline__ uint32_t smem_u32(const void* p) {
    uint32_t a;
    asm("{ .reg .u64 t; cvta.to.shared.u64 t, %1; cvt.u32.u64 %0, t; }" : "=r"(a) : "l"(p));
    return a;
}

// ---------------- mma.sync / ldmatrix helpers (sm_80+ baseline PTX) ----------------
__device__ __forceinline__ void ldsm4(uint32_t addr, uint32_t r[4]) {
    asm volatile("ldmatrix.sync.aligned.m8n8.x4.shared.b16 {%0,%1,%2,%3}, [%4];"
        : "=r"(r[0]), "=r"(r[1]), "=r"(r[2]), "=r"(r[3]) : "r"(addr));
}
__device__ __forceinline__ void ldsm4t(uint32_t addr, uint32_t r[4]) {
    asm volatile("ldmatrix.sync.aligned.m8n8.x4.trans.shared.b16 {%0,%1,%2,%3}, [%4];"
        : "=r"(r[0]), "=r"(r[1]), "=r"(r[2]), "=r"(r[3]) : "r"(addr));
}
__device__ __forceinline__ void mma_bf16(float c[4], const uint32_t a[4], uint32_t b0, uint32_t b1) {
    asm volatile("mma.sync.aligned.m16n8k16.row.col.f32.bf16.bf16.f32 "
        "{%0,%1,%2,%3}, {%4,%5,%6,%7}, {%8,%9}, {%0,%1,%2,%3};"
        : "+f"(c[0]), "+f"(c[1]), "+f"(c[2]), "+f"(c[3])
        : "r"(a[0]), "r"(a[1]), "r"(a[2]), "r"(a[3]), "r"(b0), "r"(b1));
}

// ---------------- CSR build ----------------
__global__ void k_zero() {
    int i = blockIdx.x * blockDim.x + threadIdx.x;
    if (i < KSNAP * NNODE) g_deg[i] = 0;
    if (i < KSNAP * D2)    g_emb[i] = 0.f;
}

__global__ void k_count(const int* __restrict__ ei) {
    int idx = blockIdx.x * blockDim.x + threadIdx.x;
    if (idx >= KSNAP * EPTOT) return;
    int k = idx / EPTOT, e = idx % EPTOT;
    int dst = (e < NEDGE) ? ei[(k * 2 + 1) * NEDGE + e] : (e - NEDGE);
    atomicAdd(&g_deg[k * NNODE + dst], 1);
}

__global__ void k_scan() {
    __shared__ int part[1024];
    int k = blockIdx.x, t = threadIdx.x;
    int base = t * 10;
    int loc[10];
    int s = 0;
#pragma unroll
    for (int i = 0; i < 10; i++) {
        int n = base + i;
        int v = (n < NNODE) ? g_deg[k * NNODE + n] : 0;
        loc[i] = s; s += v;
    }
    part[t] = s;
    __syncthreads();
    for (int ofs = 1; ofs < 1024; ofs <<= 1) {
        int v = (t >= ofs) ? part[t - ofs] : 0;
        __syncthreads();
        part[t] += v;
        __syncthreads();
    }
    int pre = (t == 0) ? 0 : part[t - 1];
#pragma unroll
    for (int i = 0; i < 10; i++) {
        int n = base + i;
        if (n < NNODE) {
            int o = pre + loc[i];
            g_off[k * (NNODE + 1) + n] = o;
            g_pos[k * NNODE + n]       = o;
        }
    }
    if (t == 1023) g_off[k * (NNODE + 1) + NNODE] = part[1023];
}

__global__ void k_scatter(const int* __restrict__ ei) {
    int idx = blockIdx.x * blockDim.x + threadIdx.x;
    if (idx >= KSNAP * EPTOT) return;
    int k = idx / EPTOT, e = idx % EPTOT;
    int src, dst;
    if (e < NEDGE) {
        src = ei[(k * 2 + 0) * NEDGE + e];
        dst = ei[(k * 2 + 1) * NEDGE + e];
    } else {
        src = e - NEDGE;
        dst = e - NEDGE;
    }
    int slot = atomicAdd(&g_pos[k * NNODE + dst], 1);
    g_adj[k * EPTOT + slot] = src;
}

// ---------------- prep: q vectors ----------------
__global__ void k_prep(const float* __restrict__ W1, const float* __restrict__ as1,
                       const float* __restrict__ ad1) {
    int c = threadIdx.x;
    float w = W1[c];
    float vs = warp_sum(w * as1[c]);
    float vd = warp_sum(w * ad1[c]);
    if ((c & 31) == 0) {
        g_q[c >> 5] = vs;
        g_q[8 + (c >> 5)] = vd;
    }
}

// ---------------- prep: W2 bf16 hi/lo packed [k][n/2] ----------------
__global__ void k_prepB(const float* __restrict__ W2) {
    int w = blockIdx.x * blockDim.x + threadIdx.x;   // 32768 words
    if (w >= 256 * 128) return;
    int k = w >> 7, nw = w & 127;
    float v0 = W2[k * D2 + 2 * nw];
    float v1 = W2[k * D2 + 2 * nw + 1];
    __nv_bfloat162 h2 = __float22bfloat162_rn(make_float2(v0, v1));
    float l0 = v0 - __bfloat162float(__low2bfloat16(h2));
    float l1 = v1 - __bfloat162float(__high2bfloat16(h2));
    g_Bhi[w] = *(uint32_t*)&h2;
    g_Blo[w] = pack_bf16x2(l0, l1);
}

// ---------------- layer-1 GAT (scalar) + h1 bf16 emission ----------------
__global__ __launch_bounds__(256) void k_agg1(const float* __restrict__ xs,
                                              const float* __restrict__ W1,
                                              const float* __restrict__ b1) {
    int k = blockIdx.y;
    int n = blockIdx.x * 8 + (threadIdx.x >> 5);
    int lane = threadIdx.x & 31;
    long base = (long)k * NNODE;
    int o0 = g_off[k * (NNODE + 1) + n];
    int o1 = g_off[k * (NNODE + 1) + n + 1];
    const int* adj = g_adj + (long)k * EPTOT;

    float qs[HEADS], dterm[HEADS];
    float xd = xs[base + n];
#pragma unroll
    for (int i = 0; i < HEADS; i++) { qs[i] = g_q[i]; dterm[i] = xd * g_q[8 + i]; }

    // pass 1: min/max of x over sources (exact max via monotonicity of leaky_relu)
    float xmx = -1e30f, xmn = 1e30f;
    for (int j = o0 + lane; j < o1; j += 32) {
        float xv = xs[base + adj[j]];
        xmx = fmaxf(xmx, xv); xmn = fminf(xmn, xv);
    }
    xmx = warp_max(xmx); xmn = warp_min(xmn);
    float m[HEADS];
#pragma unroll
    for (int i = 0; i < HEADS; i++)
        m[i] = lky(fmaf(qs[i], (qs[i] >= 0.f) ? xmx : xmn, dterm[i]));

    // pass 2: fused denominator + weighted sum
    float dsum[HEADS], tt[HEADS];
#pragma unroll
    for (int i = 0; i < HEADS; i++) { dsum[i] = 0.f; tt[i] = 0.f; }
    for (int j = o0 + lane; j < o1; j += 32) {
        float xv = xs[base + adj[j]];
#pragma unroll
        for (int i = 0; i < HEADS; i++) {
            float e = lky(fmaf(xv, qs[i], dterm[i]));
            float ex = __expf(e - m[i]);
            dsum[i] += ex;
            tt[i] = fmaf(ex, xv, tt[i]);
        }
    }
    float tv[HEADS];
#pragma unroll
    for (int i = 0; i < HEADS; i++) {
        float ds = warp_sum(dsum[i]);
        float ts = warp_sum(tt[i]);
        tv[i] = ts / (ds + 1e-16f);
    }

    // emit h1 = relu(W1[c]*t[head(c)] + b1[c]) as bf16, lane covers cols lane*8..+7
    int h = lane >> 2;
    float y0 = (h & 4) ? tv[4] : tv[0];
    float y1 = (h & 4) ? tv[5] : tv[1];
    float y2 = (h & 4) ? tv[6] : tv[2];
    float y3 = (h & 4) ? tv[7] : tv[3];
    float z0 = (h & 2) ? y2 : y0;
    float z1 = (h & 2) ? y3 : y1;
    float tsel = (h & 1) ? z1 : z0;

    float4 w0 = *(const float4*)&W1[lane * 8];
    float4 w1 = *(const float4*)&W1[lane * 8 + 4];
    float4 c0 = *(const float4*)&b1[lane * 8];
    float4 c1 = *(const float4*)&b1[lane * 8 + 4];
    float v0 = fmaxf(fmaf(w0.x, tsel, c0.x), 0.f);
    float v1 = fmaxf(fmaf(w0.y, tsel, c0.y), 0.f);
    float v2 = fmaxf(fmaf(w0.z, tsel, c0.z), 0.f);
    float v3 = fmaxf(fmaf(w0.w, tsel, c0.w), 0.f);
    float v4 = fmaxf(fmaf(w1.x, tsel, c1.x), 0.f);
    float v5 = fmaxf(fmaf(w1.y, tsel, c1.y), 0.f);
    float v6 = fmaxf(fmaf(w1.z, tsel, c1.z), 0.f);
    float v7 = fmaxf(fmaf(w1.w, tsel, c1.w), 0.f);
    uint4 out = make_uint4(pack_bf16x2(v0, v1), pack_bf16x2(v2, v3),
                           pack_bf16x2(v4, v5), pack_bf16x2(v6, v7));
    *(uint4*)&g_Ahi[(base + n) * 128 + lane * 4] = out;
}

// ---------------- HMMA GEMM: h_lin = h1 @ W2 (A bf16, B split hi+lo) ----------------
// smem layout (bytes): sAs[128]f32 @0, sAd[128]f32 @512, A[128][72]bf16 @1024,
//                      Bh[64][136]bf16 @19456, Bl @36864; total 54272
#define SM_AS 0
#define SM_AD 512
#define SM_A  1024
#define SM_BH 19456
#define SM_BL 36864
#define SM_TOTAL 54272

__global__ __launch_bounds__(256, 2) void k_gemm(const float* __restrict__ as2,
                                                 const float* __restrict__ ad2) {
    extern __shared__ char smem[];
    uint32_t sb = smem_u32(smem);
    int tid = threadIdx.x;
    int wid = tid >> 5, lane = tid & 31;
    int wm = wid & 3, wn = wid >> 2;
    long m0 = (long)blockIdx.x * 128;
    int ny = blockIdx.y;          // N-tile: cols ny*128..+127
    float* sAs = (float*)(smem + SM_AS);
    float* sAd = (float*)(smem + SM_AD);

    if (tid < 128) {
        sAs[tid] = as2[ny * 128 + tid];
        sAd[tid] = ad2[ny * 128 + tid];
    }

    float c_[2][8][4];
#pragma unroll
    for (int a = 0; a < 2; a++)
#pragma unroll
        for (int b = 0; b < 8; b++)
#pragma unroll
            for (int q = 0; q < 4; q++) c_[a][b][q] = 0.f;

    for (int c = 0; c < 4; c++) {   // K chunks of 64
        // load A chunk: 128 rows x 32 words
#pragma unroll
        for (int q = 0; q < 4; q++) {
            int i = tid + q * 256;
            int row = i >> 3, qq = i & 7;
            *(uint4*)(smem + SM_A + row * 144 + qq * 16) =
                *(const uint4*)&g_Ahi[(m0 + row) * 128 + c * 32 + qq * 4];
        }
        // load B chunk: 64 rows x 64 words (hi and lo)
#pragma unroll
        for (int q = 0; q < 4; q++) {
            int i = tid + q * 256;
            int row = i >> 4, qq = i & 15;
            *(uint4*)(smem + SM_BH + row * 272 + qq * 16) =
                *(const uint4*)&g_Bhi[(c * 64 + row) * 128 + ny * 64 + qq * 4];
            *(uint4*)(smem + SM_BL + row * 272 + qq * 16) =
                *(const uint4*)&g_Blo[(c * 64 + row) * 128 + ny * 64 + qq * 4];
        }
        __syncthreads();

#pragma unroll
        for (int ks = 0; ks < 4; ks++) {
            uint32_t afr[2][4];
#pragma unroll
            for (int mt = 0; mt < 2; mt++) {
                int row = wm * 32 + mt * 16 + (lane & 15);
                uint32_t addr = sb + SM_A + row * 144 + (ks * 16 + (lane >> 4) * 8) * 2;
                ldsm4(addr, afr[mt]);
            }
#pragma unroll
            for (int nt = 0; nt < 4; nt++) {
                int brow = ks * 16 + (lane & 15);
                int bcol = wn * 64 + nt * 16 + (lane >> 4) * 8;
                uint32_t bh[4], bl[4];
                ldsm4t(sb + SM_BH + brow * 272 + bcol * 2, bh);
                ldsm4t(sb + SM_BL + brow * 272 + bcol * 2, bl);
#pragma unroll
                for (int mt = 0; mt < 2; mt++) {
                    mma_bf16(c_[mt][2 * nt],     afr[mt], bh[0], bh[1]);
                    mma_bf16(c_[mt][2 * nt + 1], afr[mt], bh[2], bh[3]);
                    mma_bf16(c_[mt][2 * nt],     afr[mt], bl[0], bl[1]);
                    mma_bf16(c_[mt][2 * nt + 1], afr[mt], bl[2], bl[3]);
                }
            }
        }
        __syncthreads();
    }

    // epilogue: bf16 feature store + per-head s-vectors
    int lr = lane >> 2, lc = lane & 3;
#pragma unroll
    for (int mt = 0; mt < 2; mt++) {
        long row0 = m0 + wm * 32 + mt * 16 + lr;
        float ss0[2] = {0.f, 0.f}, ss1[2] = {0.f, 0.f};
        float sd0[2] = {0.f, 0.f}, sd1[2] = {0.f, 0.f};
#pragma unroll
        for (int p = 0; p < 8; p++) {
            int colw = ny * 64 + wn * 32 + p * 4 + lc;
            int cl = wn * 64 + p * 8 + lc * 2;
            float v0 = c_[mt][p][0], v1 = c_[mt][p][1];
            float v2 = c_[mt][p][2], v3 = c_[mt][p][3];
            g_featb[row0 * 128 + colw]       = pack_bf16x2(v0, v1);
            g_featb[(row0 + 8) * 128 + colw] = pack_bf16x2(v2, v3);
            int hs = p >> 2;
            float a0 = sAs[cl], a1 = sAs[cl + 1];
            float d0 = sAd[cl], d1 = sAd[cl + 1];
            ss0[hs] = fmaf(v0, a0, fmaf(v1, a1, ss0[hs]));
            ss1[hs] = fmaf(v2, a0, fmaf(v3, a1, ss1[hs]));
            sd0[hs] = fmaf(v0, d0, fmaf(v1, d1, sd0[hs]));
            sd1[hs] = fmaf(v2, d0, fmaf(v3, d1, sd1[hs]));
        }
#pragma unroll
        for (int hs = 0; hs < 2; hs++) {
            ss0[hs] += __shfl_xor_sync(0xffffffffu, ss0[hs], 1);
            ss0[hs] += __shfl_xor_sync(0xffffffffu, ss0[hs], 2);
            ss1[hs] += __shfl_xor_sync(0xffffffffu, ss1[hs], 1);
            ss1[hs] += __shfl_xor_sync(0xffffffffu, ss1[hs], 2);
            sd0[hs] += __shfl_xor_sync(0xffffffffu, sd0[hs], 1);
            sd0[hs] += __shfl_xor_sync(0xffffffffu, sd0[hs], 2);
            sd1[hs] += __shfl_xor_sync(0xffffffffu, sd1[hs], 1);
            sd1[hs] += __shfl_xor_sync(0xffffffffu, sd1[hs], 2);
        }
        if (lc == 0) {
            int hb = ny * 4 + wn * 2;
#pragma unroll
            for (int hs = 0; hs < 2; hs++) {
                g_ssrc[row0 * 8 + hb + hs]       = ss0[hs];
                g_ssrc[(row0 + 8) * 8 + hb + hs] = ss1[hs];
                g_sdst[row0 * 8 + hb + hs]       = sd0[hs];
                g_sdst[(row0 + 8) * 8 + hb + hs] = sd1[hs];
            }
        }
    }
}

// ---------------- layer-2 GAT aggregation + fused mean pool ----------------
__global__ __launch_bounds__(256) void k_agg2(const float* __restrict__ bias) {
    __shared__ float s_m[8][8];
    int k = blockIdx.y;
    int w = threadIdx.x >> 5;
    int n = blockIdx.x * 8 + w;
    int lane = threadIdx.x & 31;
    long base = (long)k * NNODE;
    int o0 = g_off[k * (NNODE + 1) + n];
    int o1 = g_off[k * (NNODE + 1) + n + 1];
    const int* adj = g_adj + (long)k * EPTOT;

    float sd[HEADS];
    {
        float4 d0 = *(const float4*)&g_sdst[(base + n) * HEADS];
        float4 d1 = *(const float4*)&g_sdst[(base + n) * HEADS + 4];
        sd[0] = d0.x; sd[1] = d0.y; sd[2] = d0.z; sd[3] = d0.w;
        sd[4] = d1.x; sd[5] = d1.y; sd[6] = d1.z; sd[7] = d1.w;
    }

    // pass 1: per-head max of ssrc over sources (exact; leaky is monotone)
    float mx[HEADS];
#pragma unroll
    for (int i = 0; i < HEADS; i++) mx[i] = -1e30f;
    for (int j = o0 + lane; j < o1; j += 32) {
        const float4* sp = (const float4*)&g_ssrc[((long)base + adj[j]) * HEADS];
        float4 s0 = sp[0], s1 = sp[1];
        mx[0] = fmaxf(mx[0], s0.x); mx[1] = fmaxf(mx[1], s0.y);
        mx[2] = fmaxf(mx[2], s0.z); mx[3] = fmaxf(mx[3], s0.w);
        mx[4] = fmaxf(mx[4], s1.x); mx[5] = fmaxf(mx[5], s1.y);
        mx[6] = fmaxf(mx[6], s1.z); mx[7] = fmaxf(mx[7], s1.w);
    }
#pragma unroll
    for (int i = 0; i < HEADS; i++) mx[i] = warp_max(mx[i]);
    if (lane == 0) {
#pragma unroll
        for (int i = 0; i < HEADS; i++) s_m[w][i] = lky(mx[i] + sd[i]);
    }
    __syncwarp();

    int hl = lane >> 2;
    float m_l = s_m[w][hl];
    float sd_l = sd[hl];

    // pass 2 (serial per warp): fused denominator + weighted bf16 gather
    float dsum = 0.f;
    float a0 = 0.f, a1 = 0.f, a2 = 0.f, a3 = 0.f, a4 = 0.f, a5 = 0.f, a6 = 0.f, a7 = 0.f;
    for (int j = o0; j < o1; j++) {
        long s = adj[j];
        float e = lky(g_ssrc[(base + s) * HEADS + hl] + sd_l);
        float al = __expf(e - m_l);
        dsum += al;
        uint4 fv = *(const uint4*)&g_featb[(base + s) * 128 + lane * 4];
        float2 f0 = __bfloat1622float2(*(__nv_bfloat162*)&fv.x);
        float2 f1 = __bfloat1622float2(*(__nv_bfloat162*)&fv.y);
        float2 f2 = __bfloat1622float2(*(__nv_bfloat162*)&fv.z);
        float2 f3 = __bfloat1622float2(*(__nv_bfloat162*)&fv.w);
        a0 = fmaf(f0.x, al, a0); a1 = fmaf(f0.y, al, a1);
        a2 = fmaf(f1.x, al, a2); a3 = fmaf(f1.y, al, a3);
        a4 = fmaf(f2.x, al, a4); a5 = fmaf(f2.y, al, a5);
        a6 = fmaf(f3.x, al, a6); a7 = fmaf(f3.y, al, a7);
    }
    float inv = 1.f / (dsum + 1e-16f);
    float4 b0 = *(const float4*)&bias[lane * 8];
    float4 b1v = *(const float4*)&bias[lane * 8 + 4];
    float o0v = fmaxf(fmaf(a0, inv, b0.x), 0.f);
    float o1v = fmaxf(fmaf(a1, inv, b0.y), 0.f);
    float o2v = fmaxf(fmaf(a2, inv, b0.z), 0.f);
    float o3v = fmaxf(fmaf(a3, inv, b0.w), 0.f);
    float o4v = fmaxf(fmaf(a4, inv, b1v.x), 0.f);
    float o5v = fmaxf(fmaf(a5, inv, b1v.y), 0.f);
    float o6v = fmaxf(fmaf(a6, inv, b1v.z), 0.f);
    float o7v = fmaxf(fmaf(a7, inv, b1v.w), 0.f);
    const float s = 1.0f / NNODE;
    float* ep = &g_emb[k * D2 + lane * 8];
    atomicAdd(ep + 0, o0v * s); atomicAdd(ep + 1, o1v * s);
    atomicAdd(ep + 2, o2v * s); atomicAdd(ep + 3, o3v * s);
    atomicAdd(ep + 4, o4v * s); atomicAdd(ep + 5, o5v * s);
    atomicAdd(ep + 6, o6v * s); atomicAdd(ep + 7, o7v * s);
}

// ---------------- LSTM input projections ----------------
__global__ void k_xw(const float* __restrict__ Wih_f, const float* __restrict__ Wih_b) {
    int gid = blockIdx.x * 8 + (threadIdx.x >> 5);
    int lane = threadIdx.x & 31;
    int d = gid >> 13;
    int rem = gid & 8191;
    int k = rem >> 10;
    int g = rem & 1023;
    const float* Wih = d ? Wih_b : Wih_f;
    float s = 0.f;
    for (int j = lane; j < D2; j += 32)
        s += Wih[g * D2 + j] * g_emb[k * D2 + j];
    s = warp_sum(s);
    if (lane == 0) g_xw[gid] = s;
}

__global__ void k_whhT(const float* __restrict__ Whh_f, const float* __restrict__ Whh_b) {
    int idx = blockIdx.x * blockDim.x + threadIdx.x;
    if (idx >= 2 * 128 * 1024) return;
    int d = idx >> 17;
    int r = idx & ((1 << 17) - 1);
    int j2 = r >> 10;
    int t = r & 1023;
    const float* W = d ? Whh_b : Whh_f;
    g_whhT2[(((long)d * 128 + j2) << 10) + t] = make_float2(W[t * 256 + 2 * j2], W[t * 256 + 2 * j2 + 1]);
}

// ---------------- bidirectional LSTM ----------------
__global__ __launch_bounds__(1024) void k_lstm(const float* __restrict__ bih_f, const float* __restrict__ bhh_f,
                                               const float* __restrict__ bih_b, const float* __restrict__ bhh_b,
                                               float* __restrict__ out) {
    int d = blockIdx.x;
    int t = threadIdx.x;
    __shared__ float2 h2[LH / 2];
    __shared__ float cc[LH], gbuf[4 * LH];
    if (t < LH / 2) h2[t] = make_float2(0.f, 0.f);
    if (t < LH) cc[t] = 0.f;
    const float* bih = d ? bih_b : bih_f;
    const float* bhh = d ? bhh_b : bhh_f;
    const unsigned long long* WT = (const unsigned long long*)(g_whhT2 + (long)d * 128 * 1024);
    const unsigned long long* hp = (const unsigned long long*)h2;
    float bsum = bih[t] + bhh[t];
    __syncthreads();
    for (int step = 0; step < KSNAP; step++) {
        int kk = d ? (KSNAP - 1 - step) : step;
        unsigned long long acc2 = 0ull;
#pragma unroll 8
        for (int j2 = 0; j2 < LH / 2; j2++) {
            unsigned long long w = WT[(long)j2 * 1024 + t];
            unsigned long long hh = hp[j2];
            FMA2(acc2, w, hh);
        }
        float lo, hi;
        unpack2(acc2, lo, hi);
        gbuf[t] = lo + hi + g_xw[((long)d * KSNAP + kk) * 1024 + t] + bsum;
        __syncthreads();
        if (t < LH) {
            float ig = 1.f / (1.f + expf(-gbuf[t]));
            float fg = 1.f / (1.f + expf(-gbuf[LH + t]));
            float gg = tanhf(gbuf[2 * LH + t]);
            float og = 1.f / (1.f + expf(-gbuf[3 * LH + t]));
            float cn = fg * cc[t] + ig * gg;
            cc[t] = cn;
            ((float*)h2)[t] = og * tanhf(cn);
        }
        __syncthreads();
    }
    if (t < LH) out[d * LH + t] = ((float*)h2)[t];
}

// ---------------- launch ----------------
extern "C" void kernel_launch(void* const* d_in, const int* in_sizes, int n_in,
                              void* d_out, int out_size) {
    const float* xs     = (const float*)d_in[0];
    const int*   ei     = (const int*)  d_in[1];
    const float* W1     = (const float*)d_in[2];
    const float* a_src1 = (const float*)d_in[3];
    const float* a_dst1 = (const float*)d_in[4];
    const float* b1     = (const float*)d_in[5];
    const float* W2     = (const float*)d_in[6];
    const float* a_src2 = (const float*)d_in[7];
    const float* a_dst2 = (const float*)d_in[8];
    const float* b2     = (const float*)d_in[9];
    const float* Wih_f  = (const float*)d_in[10];
    const float* Whh_f  = (const float*)d_in[11];
    const float* bih_f  = (const float*)d_in[12];
    const float* bhh_f  = (const float*)d_in[13];
    const float* Wih_b  = (const float*)d_in[14];
    const float* Whh_b  = (const float*)d_in[15];
    const float* bih_b  = (const float*)d_in[16];
    const float* bhh_b  = (const float*)d_in[17];
    float* out = (float*)d_out;

    cudaFuncSetAttribute(k_gemm, cudaFuncAttributeMaxDynamicSharedMemorySize, SM_TOTAL);

    k_zero<<<(KSNAP * NNODE + 255) / 256, 256>>>();
    k_count<<<(KSNAP * EPTOT + 255) / 256, 256>>>(ei);
    k_scan<<<KSNAP, 1024>>>();
    k_scatter<<<(KSNAP * EPTOT + 255) / 256, 256>>>(ei);

    k_prep<<<1, 256>>>(W1, a_src1, a_dst1);
    k_prepB<<<128, 256>>>(W2);

    dim3 gagg(NNODE / 8, KSNAP);
    k_agg1<<<gagg, 256>>>(xs, W1, b1);

    k_gemm<<<dim3(NTOT / 128, 2), 256, SM_TOTAL>>>(a_src2, a_dst2);
    k_agg2<<<gagg, 256>>>(b2);

    k_whhT<<<(2 * 128 * 1024 + 255) / 256, 256>>>(Whh_f, Whh_b);
    k_xw<<<2048, 256>>>(Wih_f, Wih_b);
    k_lstm<<<2, 1024>>>(bih_f, bhh_f, bih_b, bhh_b, out);
}